// round 16
// baseline (speedup 1.0000x reference)
#include <cuda_runtime.h>
#include <cuda_fp16.h>
#include <cstdint>

// Problem constants
#define B_  2
#define S_  2048
#define D_  1024
#define H_  16
#define DH_ 64
#define BS_ (B_ * S_)        // 4096
#define N3D_ (3 * D_)        // 3072

// ---------------------------------------------------------------------------
// Scratch (allocation-free: __device__ globals) — all fp16
// ---------------------------------------------------------------------------
__device__ __align__(128) __half g_Qh[B_ * H_ * S_ * DH_];  // scaled 0.125
__device__ __align__(128) __half g_Kh[B_ * H_ * S_ * DH_];
__device__ __align__(128) __half g_Vh[B_ * H_ * S_ * DH_];
__device__ __align__(128) __half g_xh[BS_ * D_];
__device__ __align__(128) __half g_WqTh[N3D_ * D_];
__device__ __align__(128) __half g_WpTh[D_ * D_];
__device__ __align__(128) __half g_Oh[BS_ * D_];

// ---------------------------------------------------------------------------
// Base-ISA helpers
// ---------------------------------------------------------------------------
__device__ __forceinline__ uint32_t smem_u32(const void* p) {
    uint32_t a;
    asm("{ .reg .u64 t; cvta.to.shared.u64 t, %1; cvt.u32.u64 %0, t; }"
        : "=r"(a) : "l"(p));
    return a;
}
__device__ __forceinline__ uint32_t swz(uint32_t b) { return b ^ ((b >> 3) & 0x70); }

__device__ __forceinline__ void ldm4(uint32_t& r0, uint32_t& r1, uint32_t& r2,
                                     uint32_t& r3, uint32_t a) {
    asm volatile("ldmatrix.sync.aligned.m8n8.x4.shared.b16 {%0,%1,%2,%3},[%4];"
                 : "=r"(r0), "=r"(r1), "=r"(r2), "=r"(r3) : "r"(a));
}
__device__ __forceinline__ void ldm4t(uint32_t& r0, uint32_t& r1, uint32_t& r2,
                                      uint32_t& r3, uint32_t a) {
    asm volatile("ldmatrix.sync.aligned.m8n8.x4.trans.shared.b16 {%0,%1,%2,%3},[%4];"
                 : "=r"(r0), "=r"(r1), "=r"(r2), "=r"(r3) : "r"(a));
}
__device__ __forceinline__ void mma16816h(float* d, const uint32_t* a,
                                          const uint32_t* b) {
    asm volatile(
        "mma.sync.aligned.m16n8k16.row.col.f32.f16.f16.f32 "
        "{%0,%1,%2,%3},{%4,%5,%6,%7},{%8,%9},{%0,%1,%2,%3};"
        : "+f"(d[0]), "+f"(d[1]), "+f"(d[2]), "+f"(d[3])
        : "r"(a[0]), "r"(a[1]), "r"(a[2]), "r"(a[3]), "r"(b[0]), "r"(b[1]));
}
__device__ __forceinline__ void cp16(uint32_t dst, const void* src) {
    asm volatile("cp.async.cg.shared.global [%0],[%1],16;" :: "r"(dst), "l"(src));
}
#define CP_COMMIT() asm volatile("cp.async.commit_group;")

__device__ __forceinline__ uint32_t packh2(float a, float b) {
    __half2 h = __floats2half2_rn(a, b);
    return *(uint32_t*)&h;
}

// ---------------------------------------------------------------------------
// Fused prep: blocks [0,2048) split x; [2048,5120) Wqkv^T; [5120,6144) Wproj^T.
// ---------------------------------------------------------------------------
__global__ void __launch_bounds__(256) prep_kernel(
    const float* __restrict__ x,
    const float* __restrict__ Wqkv,
    const float* __restrict__ Wproj)
{
    const int bid = blockIdx.x;
    const int tid = threadIdx.x;

    if (bid < 2048) {
        const int n4 = BS_ * D_ / 4;
        for (int i = bid * 256 + tid; i < n4; i += 2048 * 256) {
            float4 f = ((const float4*)x)[i];
            uint2 o;
            o.x = packh2(f.x, f.y);
            o.y = packh2(f.z, f.w);
            ((uint2*)g_xh)[i] = o;
        }
        return;
    }

    __shared__ float t[32][33];
    const int tx = tid & 31;
    const int ty = tid >> 5;

    const float* W;
    __half* dst;
    int K = D_, N;
    int tile;
    if (bid < 5120) {
        W = Wqkv; dst = g_WqTh; N = N3D_;
        tile = bid - 2048;
    } else {
        W = Wproj; dst = g_WpTh; N = D_;
        tile = bid - 5120;
    }
    const int ntx = N / 32;
    const int n0 = (tile % ntx) * 32;
    const int k0 = (tile / ntx) * 32;

#pragma unroll
    for (int r = 0; r < 32; r += 8)
        t[ty + r][tx] = W[(size_t)(k0 + ty + r) * N + n0 + tx];
    __syncthreads();
#pragma unroll
    for (int r = 0; r < 32; r += 8)
        dst[(size_t)(n0 + ty + r) * K + k0 + tx] = __float2half(t[tx][ty + r]);
}

// ---------------------------------------------------------------------------
// Tile loader (256 threads): 128 rows x 64 fp16 (128B swizzled rows), ld=1024
// ---------------------------------------------------------------------------
__device__ __forceinline__ void cp_tile128(uint32_t sdst,
                                           const __half* __restrict__ g,
                                           int row0, int k0, int tid)
{
#pragma unroll
    for (int it = 0; it < 4; it++) {
        int idx = tid + it * 256;
        int row = idx >> 3;
        int c   = idx & 7;
        cp16(sdst + swz(row * 128 + c * 16),
             g + (size_t)(row0 + row) * 1024 + k0 + c * 8);
    }
}

// ---------------------------------------------------------------------------
// fp16 single-pass GEMM. 128x128 CTA tile, 8 warps (4x2), 32x64 warp tile,
// K-chunk 64, 3-STAGE cp.async pipeline (32KB/stage, 96KB) -> 2 CTAs/SM.
// MODE 0: QKV -> scatter g_Qh/g_Kh/g_Vh (+bias, Q scaled)
// MODE 1: proj -> Cout fp32 (+bias)
// ---------------------------------------------------------------------------
#define GA_BYTES (128 * 64 * 2)              // 16384
#define GSTAGE   (2 * GA_BYTES)              // 32768 (A + B)
#define GEMM_DSMEM (3 * GSTAGE)              // 98304

template <int MODE>
__global__ void __launch_bounds__(256, 2) gemm_h(
    const float* __restrict__ bias, float* __restrict__ Cout)
{
    constexpr int N = (MODE == 0) ? N3D_ : D_;
    constexpr int nkc = D_ / 64;    // 16
    extern __shared__ char dsm[];
    const uint32_t sb0 = smem_u32(dsm);

    const int tid = threadIdx.x;
    const int wid = tid >> 5;
    const int lid = tid & 31;
    const int wm = wid >> 1;        // 0..3
    const int wn = wid & 1;         // 0..1
    const int m0 = blockIdx.y * 128;
    const int n0 = blockIdx.x * 128;

    const __half* A  = (MODE == 0) ? g_xh : g_Oh;
    const __half* Bm = (MODE == 0) ? g_WqTh : g_WpTh;

    const int a_row = (lid & 7) + ((lid >> 3) & 1) * 8;
    const int a_kb  = (lid >> 4) * 16;
    const int b_row = (lid & 7) + ((lid >> 4) & 1) * 8;
    const int b_kb  = ((lid >> 3) & 1) * 16;

    float acc[2][8][4];
#pragma unroll
    for (int i = 0; i < 2; i++)
#pragma unroll
        for (int j = 0; j < 8; j++)
#pragma unroll
            for (int r = 0; r < 4; r++) acc[i][j][r] = 0.f;

    // prologue: stages 0,1 (two commit groups)
#pragma unroll
    for (int s = 0; s < 2; s++) {
        uint32_t sb = sb0 + s * GSTAGE;
        cp_tile128(sb + 0,        A,  m0, s * 64, tid);
        cp_tile128(sb + GA_BYTES, Bm, n0, s * 64, tid);
        CP_COMMIT();
    }

    int bufc = 0;   // kc % 3
    int bufp = 2;   // (kc+2) % 3
    for (int kc = 0; kc < nkc; kc++) {
        if (kc + 1 < nkc) { asm volatile("cp.async.wait_group 1;"); }
        else              { asm volatile("cp.async.wait_group 0;"); }
        __syncthreads();   // stage kc ready; all warps done with stage kc-1

        if (kc + 2 < nkc) {
            uint32_t sb = sb0 + bufp * GSTAGE;
            const int k0 = (kc + 2) * 64;
            cp_tile128(sb + 0,        A,  m0, k0, tid);
            cp_tile128(sb + GA_BYTES, Bm, n0, k0, tid);
            CP_COMMIT();
        }

        const uint32_t sb = sb0 + bufc * GSTAGE;
        const uint32_t sA = sb;
        const uint32_t sB = sb + GA_BYTES;

#pragma unroll
        for (int ks = 0; ks < 4; ks++) {
            uint32_t ah[2][4], bh[8][2];
#pragma unroll
            for (int i = 0; i < 2; i++) {
                uint32_t off = swz((wm * 32 + i * 16 + a_row) * 128 + ks * 32 + a_kb);
                ldm4(ah[i][0], ah[i][1], ah[i][2], ah[i][3], sA + off);
            }
#pragma unroll
            for (int p = 0; p < 4; p++) {
                uint32_t off = swz((wn * 64 + p * 16 + b_row) * 128 + ks * 32 + b_kb);
                ldm4(bh[2 * p][0], bh[2 * p][1], bh[2 * p + 1][0],
                     bh[2 * p + 1][1], sB + off);
            }
#pragma unroll
            for (int i = 0; i < 2; i++)
#pragma unroll
                for (int j = 0; j < 8; j++)
                    mma16816h(acc[i][j], ah[i], bh[j]);
        }
        bufc = (bufc == 2) ? 0 : bufc + 1;
        bufp = (bufp == 2) ? 0 : bufp + 1;
    }

#pragma unroll
    for (int i = 0; i < 2; i++) {
#pragma unroll
        for (int j = 0; j < 8; j++) {
            const int n = n0 + wn * 64 + j * 8 + (lid & 3) * 2;
            const float b0 = __ldg(&bias[n]);
            const float b1 = __ldg(&bias[n + 1]);
#pragma unroll
            for (int rr = 0; rr < 2; rr++) {
                const int m = m0 + wm * 32 + i * 16 + (lid >> 2) + rr * 8;
                float v0 = acc[i][j][rr * 2 + 0] + b0;
                float v1 = acc[i][j][rr * 2 + 1] + b1;
                if constexpr (MODE == 0) {
                    const int b = m >> 11, s = m & 2047;
                    const int rem = n & 1023, h = rem >> 6, d = rem & 63;
                    const size_t o = (((size_t)(b * H_ + h) << 11) + s) * DH_ + d;
                    const int which = n0 >> 10;
                    if (which == 0) { v0 *= 0.125f; v1 *= 0.125f; }
                    const uint32_t hp = packh2(v0, v1);
                    if (which == 0)      *(uint32_t*)(g_Qh + o) = hp;
                    else if (which == 1) *(uint32_t*)(g_Kh + o) = hp;
                    else                 *(uint32_t*)(g_Vh + o) = hp;
                } else {
                    *(float2*)(Cout + (size_t)m * N + n) = make_float2(v0, v1);
                }
            }
        }
    }
}

// ---------------------------------------------------------------------------
// Flash attention, fp16 single-pass, BN=128 key tiles, LPT order (unchanged).
// ---------------------------------------------------------------------------
#define FBM 128
#define FBN 128
#define FK_BYTES (FBN * 128)            // 16384
#define FSTAGE   (2 * FK_BYTES)          // 32768
#define FLASH_DSMEM (3 * FSTAGE)         // 98304

__device__ __forceinline__ void cp_ftile(uint32_t sdst,
                                         const __half* __restrict__ g,
                                         int tid)
{
#pragma unroll
    for (int it = 0; it < 4; it++) {
        int idx = tid + it * 256;
        int row = idx >> 3;
        int c   = idx & 7;
        cp16(sdst + swz(row * 128 + c * 16), g + (size_t)row * 64 + c * 8);
    }
}

__global__ void __launch_bounds__(256) flash_mma_kernel()
{
    extern __shared__ char fsm[];
    const uint32_t sStage = smem_u32(fsm);

    const int tid = threadIdx.x;
    const int wid = tid >> 5;
    const int lid = tid & 31;
    const int qt = gridDim.x - 1 - blockIdx.x;   // heavy tiles first (LPT)
    const int bh = blockIdx.y;
    const int q0 = qt * FBM;
    const int nkt = qt + 1;

    const __half* Qg = g_Qh + ((size_t)bh * S_ + q0) * DH_;
    const __half* Kg = g_Kh + (size_t)bh * S_ * DH_;
    const __half* Vg = g_Vh + (size_t)bh * S_ * DH_;

#pragma unroll
    for (int it = 0; it < 4; it++) {
        int idx = tid + it * 256;
        int row = idx >> 3;
        int c   = idx & 7;
        cp16(sStage + swz(row * 128 + c * 16), Qg + (size_t)row * 64 + c * 8);
    }
    CP_COMMIT();
    asm volatile("cp.async.wait_group 0;");
    __syncthreads();

    const int a_row = (lid & 7) + ((lid >> 3) & 1) * 8;
    const int a_kb  = (lid >> 4) * 16;
    uint32_t qh[4][4];
#pragma unroll
    for (int ks = 0; ks < 4; ks++) {
        uint32_t off = swz((wid * 16 + a_row) * 128 + ks * 32 + a_kb);
        ldm4(qh[ks][0], qh[ks][1], qh[ks][2], qh[ks][3], sStage + off);
    }
    __syncthreads();

#pragma unroll
    for (int s = 0; s < 2; s++) {
        uint32_t sb = sStage + s * FSTAGE;
        const size_t koff = (size_t)s * FBN * DH_;
        cp_ftile(sb + 0,        Kg + koff, tid);
        cp_ftile(sb + FK_BYTES, Vg + koff, tid);
        CP_COMMIT();
    }

    const int b_row = (lid & 7) + ((lid >> 4) & 1) * 8;
    const int b_kb  = ((lid >> 3) & 1) * 16;
    const int v_row = (lid & 7) + ((lid >> 3) & 1) * 8;
    const int v_cb  = ((lid >> 4) & 1) * 16;

    float m_i[2] = {-1e30f, -1e30f};
    float l_i[2] = {0.f, 0.f};
    float out[8][4];
#pragma unroll
    for (int nn = 0; nn < 8; nn++)
#pragma unroll
        for (int r = 0; r < 4; r++) out[nn][r] = 0.f;

    int bufc = 0;
    int bufp = 2;
    for (int kt = 0; kt < nkt; kt++) {
        if (kt + 1 < nkt) { asm volatile("cp.async.wait_group 1;"); }
        else              { asm volatile("cp.async.wait_group 0;"); }
        __syncthreads();

        if (kt + 2 < nkt) {
            uint32_t sb2 = sStage + bufp * FSTAGE;
            const size_t koff = (size_t)(kt + 2) * FBN * DH_;
            cp_ftile(sb2 + 0,        Kg + koff, tid);
            cp_ftile(sb2 + FK_BYTES, Vg + koff, tid);
            CP_COMMIT();
        }

        const uint32_t sb = sStage + bufc * FSTAGE;
        const uint32_t sK = sb;
        const uint32_t sV = sb + FK_BYTES;

        float sc[16][4];
#pragma unroll
        for (int j = 0; j < 16; j++)
#pragma unroll
            for (int r = 0; r < 4; r++) sc[j][r] = 0.f;

#pragma unroll
        for (int jp = 0; jp < 8; jp++) {
#pragma unroll
            for (int ks = 0; ks < 4; ks++) {
                uint32_t off = swz((jp * 16 + b_row) * 128 + ks * 32 + b_kb);
                uint32_t kh[4];
                ldm4(kh[0], kh[1], kh[2], kh[3], sK + off);
                mma16816h(sc[2 * jp],     qh[ks], &kh[0]);
                mma16816h(sc[2 * jp + 1], qh[ks], &kh[2]);
            }
        }

        if (kt == nkt - 1) {
            const int k0g = kt * FBN;
            const int rbase = q0 + wid * 16 + (lid >> 2);
#pragma unroll
            for (int j = 0; j < 16; j++) {
                const int cbase = k0g + j * 8 + 2 * (lid & 3);
#pragma unroll
                for (int rr = 0; rr < 2; rr++) {
                    const int row = rbase + rr * 8;
                    if (cbase > row)     sc[j][2 * rr]     = -1e30f;
                    if (cbase + 1 > row) sc[j][2 * rr + 1] = -1e30f;
                }
            }
        }

        float alpha[2];
#pragma unroll
        for (int rr = 0; rr < 2; rr++) {
            float tm = -1e30f;
#pragma unroll
            for (int j = 0; j < 16; j++)
                tm = fmaxf(tm, fmaxf(sc[j][2 * rr], sc[j][2 * rr + 1]));
            tm = fmaxf(tm, __shfl_xor_sync(0xffffffffu, tm, 1));
            tm = fmaxf(tm, __shfl_xor_sync(0xffffffffu, tm, 2));
            const float mn = fmaxf(m_i[rr], tm);
            alpha[rr] = __expf(m_i[rr] - mn);
            m_i[rr] = mn;
            float rs = 0.f;
#pragma unroll
            for (int j = 0; j < 16; j++) {
                float p0 = __expf(sc[j][2 * rr]     - mn);
                float p1 = __expf(sc[j][2 * rr + 1] - mn);
                sc[j][2 * rr] = p0; sc[j][2 * rr + 1] = p1;
                rs += p0 + p1;
            }
            rs += __shfl_xor_sync(0xffffffffu, rs, 1);
            rs += __shfl_xor_sync(0xffffffffu, rs, 2);
            l_i[rr] = l_i[rr] * alpha[rr] + rs;
        }
#pragma unroll
        for (int nn = 0; nn < 8; nn++) {
            out[nn][0] *= alpha[0]; out[nn][1] *= alpha[0];
            out[nn][2] *= alpha[1]; out[nn][3] *= alpha[1];
        }

#pragma unroll
        for (int kk = 0; kk < 8; kk++) {
            uint32_t ph[4];
            ph[0] = packh2(sc[2 * kk][0],     sc[2 * kk][1]);
            ph[1] = packh2(sc[2 * kk][2],     sc[2 * kk][3]);
            ph[2] = packh2(sc[2 * kk + 1][0], sc[2 * kk + 1][1]);
            ph[3] = packh2(sc[2 * kk + 1][2], sc[2 * kk + 1][3]);
#pragma unroll
            for (int np = 0; np < 4; np++) {
                uint32_t off = swz((kk * 16 + v_row) * 128 + np * 32 + v_cb);
                uint32_t vh[4];
                ldm4t(vh[0], vh[1], vh[2], vh[3], sV + off);
                mma16816h(out[2 * np],     ph, &vh[0]);
                mma16816h(out[2 * np + 1], ph, &vh[2]);
            }
        }

        bufc = (bufc == 2) ? 0 : bufc + 1;
        bufp = (bufp == 2) ? 0 : bufp + 1;
    }

    const int b = bh >> 4;
    const int h = bh & 15;
    const float inv0 = 1.0f / l_i[0];
    const float inv1 = 1.0f / l_i[1];
#pragma unroll
    for (int nn = 0; nn < 8; nn++) {
        const int col = h * 64 + nn * 8 + 2 * (lid & 3);
#pragma unroll
        for (int rr = 0; rr < 2; rr++) {
            const int row = q0 + wid * 16 + (lid >> 2) + rr * 8;
            const float inv = rr ? inv1 : inv0;
            const size_t o = ((size_t)b * S_ + row) * D_ + col;
            *(uint32_t*)(g_Oh + o) =
                packh2(out[nn][2 * rr] * inv, out[nn][2 * rr + 1] * inv);
        }
    }
}

// ---------------------------------------------------------------------------
// Launch
// ---------------------------------------------------------------------------
extern "C" void kernel_launch(void* const* d_in, const int* in_sizes, int n_in,
                              void* d_out, int out_size)
{
    const float* x     = (const float*)d_in[0];
    const float* Wqkv  = (const float*)d_in[1];
    const float* bqkv  = (const float*)d_in[2];
    const float* Wproj = (const float*)d_in[3];
    const float* bproj = (const float*)d_in[4];
    float* out = (float*)d_out;

    cudaFuncSetAttribute(gemm_h<0>,
                         cudaFuncAttributeMaxDynamicSharedMemorySize, GEMM_DSMEM);
    cudaFuncSetAttribute(gemm_h<1>,
                         cudaFuncAttributeMaxDynamicSharedMemorySize, GEMM_DSMEM);
    cudaFuncSetAttribute(flash_mma_kernel,
                         cudaFuncAttributeMaxDynamicSharedMemorySize, FLASH_DSMEM);

    prep_kernel<<<6144, 256>>>(x, Wqkv, Wproj);

    gemm_h<0><<<dim3(N3D_ / 128, BS_ / 128), 256, GEMM_DSMEM>>>(bqkv, nullptr);

    flash_mma_kernel<<<dim3(S_ / FBM, B_ * H_), 256, FLASH_DSMEM>>>();

    gemm_h<1><<<dim3(D_ / 128, BS_ / 128), 256, GEMM_DSMEM>>>(bproj, out);
}